// round 15
// baseline (speedup 1.0000x reference)
#include <cuda_runtime.h>
#include <cuda_bf16.h>

#define NV  3
#define NN  4096
#define HH  256
#define CC  20
#define DYY 300
#define DD  512

// ---------------- scratch (static device globals) ---------------------------
__device__ float g_xp[(size_t)NV * NN * HH];   // leaky(x@W^T+b)  (fp32)
__device__ float g_xq[(size_t)NV * NN * HH];   // normalized, tf32-rounded
__device__ float g_xb[(size_t)NV * NN * HH];   // xp*colmask, tf32-rounded
__device__ float g_s [(size_t)NN * NN];        // max_v exp(...), tf32-rounded
__device__ float g_rowsum[NN];
__device__ float g_yn[CC * HH];
__device__ float g_xr[(size_t)NV * NN * DD];   // x rounded to tf32
__device__ float g_wr[(size_t)NV * HH * DD];   // W rounded to tf32

struct ProjPtrs {
    const float* b[NV];
    const int*   mask;
};
struct RoundPtrs {
    const float* x[NV];
    const float* W[NV];
};

// ---------------- helpers ---------------------------------------------------
__device__ __forceinline__ unsigned f2tf(float f) {
    unsigned u;
    asm("cvt.rna.tf32.f32 %0, %1;" : "=r"(u) : "f"(f));
    return u;
}
__device__ __forceinline__ float f2tf_f(float f) { return __uint_as_float(f2tf(f)); }

__device__ __forceinline__ void mma_tf32(float* d, const unsigned* a, const unsigned* b) {
    asm volatile(
        "mma.sync.aligned.m16n8k8.row.col.f32.tf32.tf32.f32 "
        "{%0,%1,%2,%3},{%4,%5,%6,%7},{%8,%9},{%0,%1,%2,%3};"
        : "+f"(d[0]), "+f"(d[1]), "+f"(d[2]), "+f"(d[3])
        : "r"(a[0]), "r"(a[1]), "r"(a[2]), "r"(a[3]), "r"(b[0]), "r"(b[1]));
}

__device__ __forceinline__ void ldsm4(unsigned* r, const void* p) {
    unsigned a = (unsigned)__cvta_generic_to_shared(p);
    asm volatile("ldmatrix.sync.aligned.m8n8.x4.shared.b16 {%0,%1,%2,%3}, [%4];"
                 : "=r"(r[0]), "=r"(r[1]), "=r"(r[2]), "=r"(r[3]) : "r"(a));
}

__device__ __forceinline__ void cp16(float* dst, const float* src) {
    unsigned d = (unsigned)__cvta_generic_to_shared(dst);
    asm volatile("cp.async.cg.shared.global [%0], [%1], 16;" :: "r"(d), "l"(src) : "memory");
}
#define CP_COMMIT() asm volatile("cp.async.commit_group;" ::: "memory")
#define CP_WAIT0()  asm volatile("cp.async.wait_group 0;" ::: "memory")

// ---------------- K-1: round x, W to tf32 in gmem ---------------------------
__global__ void k_round(RoundPtrs R) {
    const int XN4 = NN * DD / 4, WN4 = HH * DD / 4;
    int idx = blockIdx.x * 256 + threadIdx.x;
    float4 f;
    float* dst;
    if (idx < 3 * XN4) {
        int v = idx / XN4, r = idx % XN4;
        f = ((const float4*)R.x[v])[r];
        dst = g_xr + (size_t)v * NN * DD + (size_t)r * 4;
    } else if (idx < 3 * XN4 + 3 * WN4) {
        int t = idx - 3 * XN4;
        int v = t / WN4, r = t % WN4;
        f = ((const float4*)R.W[v])[r];
        dst = g_wr + (size_t)v * HH * DD + (size_t)r * 4;
    } else return;
    f.x = f2tf_f(f.x); f.y = f2tf_f(f.y); f.z = f2tf_f(f.z); f.w = f2tf_f(f.w);
    *(float4*)dst = f;
}

// ---------------- K0: y_n = sigmoid(y @ Wy^T + by) --------------------------
__global__ void k_yn(const float* __restrict__ y,
                     const float* __restrict__ Wy,
                     const float* __restrict__ by) {
    int c = blockIdx.x;
    int h = threadIdx.x;
    __shared__ float ys[DYY];
    for (int d = threadIdx.x; d < DYY; d += blockDim.x) ys[d] = y[c * DYY + d];
    __syncthreads();
    const float* wr = Wy + (size_t)h * DYY;
    float acc = 0.f;
#pragma unroll 4
    for (int d = 0; d < DYY; d++) acc = fmaf(ys[d], wr[d], acc);
    acc += by[h];
    g_yn[c * HH + h] = 1.f / (1.f + __expf(-acc));
}

// ---------------- K1: tensor-core proj: xp / xq / xb ------------------------
// Block 128 rows x 256 cols (full H). 512 threads, 16 warps 4x4, warp 32x64.
// grid (32, 3) = 96 blocks -> single wave on 148 SMs.
#define PROJ_ABUF (128 * 36)
#define PROJ_BBUF (256 * 36)
__global__ __launch_bounds__(512, 1) void k_proj_tc(ProjPtrs P) {
    int v = blockIdx.y, rb = blockIdx.x;
    int tid = threadIdx.x, lane = tid & 31, wid = tid >> 5;
    int wm = wid >> 2, wn = wid & 3;
    int g = lane >> 2, tg = lane & 3;

    extern __shared__ float dyn[];
    float* Abuf = dyn;                          // [2][128*36]
    float* Bbuf = dyn + 2 * PROJ_ABUF;          // [2][256*36]
    __shared__ float ss[4][128];

    const float* xr = g_xr + (size_t)v * NN * DD;
    const float* wr = g_wr + (size_t)v * HH * DD;

    auto load_chunk = [&](int c, int buf) {
        int k0 = c * 32;
        float* A = Abuf + buf * PROJ_ABUF;
        float* B = Bbuf + buf * PROJ_BBUF;
#pragma unroll
        for (int q = 0; q < 2; q++) {           // A: 128x32 = 1024 f4
            int l = q * 512 + tid;
            int r = l >> 3, kq = l & 7;
            cp16(A + r * 36 + kq * 4, xr + (size_t)(rb * 128 + r) * DD + k0 + kq * 4);
        }
#pragma unroll
        for (int q = 0; q < 4; q++) {           // B: 256x32 = 2048 f4
            int l = q * 512 + tid;
            int r = l >> 3, kq = l & 7;
            cp16(B + r * 36 + kq * 4, wr + (size_t)r * DD + k0 + kq * 4);
        }
        CP_COMMIT();
    };

    float acc[16][4];
#pragma unroll
    for (int t = 0; t < 16; t++)
#pragma unroll
        for (int e = 0; e < 4; e++) acc[t][e] = 0.f;

    load_chunk(0, 0);
    for (int c = 0; c < DD / 32; c++) {
        CP_WAIT0();
        __syncthreads();
        if (c < DD / 32 - 1) load_chunk(c + 1, (c + 1) & 1);
        const float* A = Abuf + (c & 1) * PROJ_ABUF;
        const float* B = Bbuf + (c & 1) * PROJ_BBUF;
#pragma unroll
        for (int ks = 0; ks < 4; ks++) {
            unsigned a[2][4], b[8][2];
#pragma unroll
            for (int i = 0; i < 2; i++)
                ldsm4(a[i], A + (wm * 32 + i * 16 + (lane & 15)) * 36
                              + ks * 8 + ((lane >> 4) & 1) * 4);
#pragma unroll
            for (int jp = 0; jp < 4; jp++) {
                unsigned t[4];
                ldsm4(t, B + (wn * 64 + jp * 16 + (lane & 7) + ((lane >> 4) & 1) * 8) * 36
                           + ks * 8 + ((lane >> 3) & 1) * 4);
                b[jp * 2][0] = t[0]; b[jp * 2][1] = t[1];
                b[jp * 2 + 1][0] = t[2]; b[jp * 2 + 1][1] = t[3];
            }
#pragma unroll
            for (int i = 0; i < 2; i++)
#pragma unroll
                for (int j = 0; j < 8; j++)
                    mma_tf32(acc[i * 8 + j], a[i], b[j]);
        }
    }

    // epilogue: bias + leaky, per-row sumsq (4 lanes shfl + cross-warp smem)
    float bcol[16];
#pragma unroll
    for (int j = 0; j < 8; j++) {
        bcol[j * 2]     = P.b[v][wn * 64 + j * 8 + 2 * tg];
        bcol[j * 2 + 1] = P.b[v][wn * 64 + j * 8 + 2 * tg + 1];
    }
    float ssq[4];
#pragma unroll
    for (int i = 0; i < 2; i++)
#pragma unroll
        for (int hh = 0; hh < 2; hh++) {
            float s = 0.f;
#pragma unroll
            for (int j = 0; j < 8; j++)
#pragma unroll
                for (int e = 0; e < 2; e++) {
                    float t = acc[i * 8 + j][hh * 2 + e] + bcol[j * 2 + e];
                    t = (t >= 0.f) ? t : 0.1f * t;
                    acc[i * 8 + j][hh * 2 + e] = t;
                    s = fmaf(t, t, s);
                }
            ssq[i * 2 + hh] = s;
        }
#pragma unroll
    for (int r4 = 0; r4 < 4; r4++) {
        ssq[r4] += __shfl_xor_sync(0xFFFFFFFFu, ssq[r4], 1);
        ssq[r4] += __shfl_xor_sync(0xFFFFFFFFu, ssq[r4], 2);
    }
    if (tg == 0) {
#pragma unroll
        for (int i = 0; i < 2; i++)
#pragma unroll
            for (int hh = 0; hh < 2; hh++)
                ss[wn][wm * 32 + i * 16 + hh * 8 + g] = ssq[i * 2 + hh];
    }
    __syncthreads();
#pragma unroll
    for (int i = 0; i < 2; i++)
#pragma unroll
        for (int hh = 0; hh < 2; hh++) {
            int lr = wm * 32 + i * 16 + hh * 8 + g;
            int n = rb * 128 + lr;
            float tot = (ss[0][lr] + ss[1][lr]) + (ss[2][lr] + ss[3][lr]);
            float rinv = 1.f / fmaxf(sqrtf(tot), 1e-12f);
            float mrow = (float)P.mask[n * NV + v];
            size_t base = ((size_t)v * NN + n) * HH;
#pragma unroll
            for (int j = 0; j < 8; j++) {
                int col = wn * 64 + j * 8 + 2 * tg;
                float p0 = acc[i * 8 + j][hh * 2];
                float p1 = acc[i * 8 + j][hh * 2 + 1];
                *(float2*)(g_xp + base + col) = make_float2(p0, p1);
                *(float2*)(g_xq + base + col) =
                    make_float2(f2tf_f(p0 * rinv), f2tf_f(p1 * rinv));
                *(float2*)(g_xb + base + col) =
                    make_float2(f2tf_f(p0 * mrow), f2tf_f(p1 * mrow));
            }
        }
}

// ---------------- K2: s = max_v exp(xq_v @ xq_v^T / beta)*masks, diag=0 ----
// Block 128x128, 512 threads, 16 warps 4x4, warp tile 32x32 -> 64 accum regs
// per thread (vs 128 before) -> 16 warps/SM instead of 8.
#define SMAT_BUF (128 * 36)
__global__ __launch_bounds__(512, 1) void k_smat_tc(const int* __restrict__ mask) {
    int cb = blockIdx.x, rb = blockIdx.y;
    int tid = threadIdx.x, lane = tid & 31, wid = tid >> 5;
    int wm = wid >> 2, wn = wid & 3;
    int g = lane >> 2, tg = lane & 3;

    extern __shared__ float dyn[];
    float* Abuf = dyn;
    float* Bbuf = dyn + 2 * SMAT_BUF;

    __shared__ int rm_s[NV][128], cm_s[NV][128];
    for (int l = tid; l < 128; l += 512) {
#pragma unroll
        for (int v = 0; v < NV; v++) {
            rm_s[v][l] = mask[(rb * 128 + l) * NV + v];
            cm_s[v][l] = mask[(cb * 128 + l) * NV + v];
        }
    }

    auto load_chunk = [&](int c, int buf) {
        int v = c >> 3, k0 = (c & 7) * 32;
        const float* xq = g_xq + (size_t)v * NN * HH;
        float* Ab = Abuf + buf * SMAT_BUF;
        float* Bb = Bbuf + buf * SMAT_BUF;
#pragma unroll
        for (int q = 0; q < 2; q++) {
            int l = q * 512 + tid;
            int r = l >> 3, kq = l & 7;
            cp16(Ab + r * 36 + kq * 4, xq + (size_t)(rb * 128 + r) * HH + k0 + kq * 4);
            cp16(Bb + r * 36 + kq * 4, xq + (size_t)(cb * 128 + r) * HH + k0 + kq * 4);
        }
        CP_COMMIT();
    };

    float smax[8][4], dot[8][4];
#pragma unroll
    for (int t = 0; t < 8; t++)
#pragma unroll
        for (int e = 0; e < 4; e++) { smax[t][e] = 0.f; dot[t][e] = 0.f; }

    load_chunk(0, 0);

    for (int c = 0; c < 24; c++) {
        CP_WAIT0();
        __syncthreads();
        if (c < 23) load_chunk(c + 1, (c + 1) & 1);

        const float* As = Abuf + (c & 1) * SMAT_BUF;
        const float* Bs = Bbuf + (c & 1) * SMAT_BUF;
#pragma unroll
        for (int ks = 0; ks < 4; ks++) {
            unsigned a[2][4], b[4][2];
#pragma unroll
            for (int i = 0; i < 2; i++)
                ldsm4(a[i], As + (wm * 32 + i * 16 + (lane & 15)) * 36
                              + ks * 8 + ((lane >> 4) & 1) * 4);
#pragma unroll
            for (int jp = 0; jp < 2; jp++) {
                unsigned t[4];
                ldsm4(t, Bs + (wn * 32 + jp * 16 + (lane & 7) + ((lane >> 4) & 1) * 8) * 36
                           + ks * 8 + ((lane >> 3) & 1) * 4);
                b[jp * 2][0] = t[0]; b[jp * 2][1] = t[1];
                b[jp * 2 + 1][0] = t[2]; b[jp * 2 + 1][1] = t[3];
            }
#pragma unroll
            for (int i = 0; i < 2; i++)
#pragma unroll
                for (int j = 0; j < 4; j++)
                    mma_tf32(dot[i * 4 + j], a[i], b[j]);
        }

        if ((c & 7) == 7) {                 // view boundary: merge + reset
            int v = c >> 3;
#pragma unroll
            for (int i = 0; i < 2; i++)
#pragma unroll
                for (int j = 0; j < 4; j++) {
                    int t = i * 4 + j;
#pragma unroll
                    for (int e = 0; e < 4; e++) {
                        int rl = wm * 32 + i * 16 + g + ((e >> 1) << 3);
                        int cl = wn * 32 + j * 8 + 2 * tg + (e & 1);
                        if (rm_s[v][rl] && cm_s[v][cl])
                            smax[t][e] = fmaxf(smax[t][e], __expf(dot[t][e] * 5.0f));
                        dot[t][e] = 0.f;
                    }
                }
        }
    }

#pragma unroll
    for (int i = 0; i < 2; i++)
#pragma unroll
        for (int j = 0; j < 4; j++) {
            int t = i * 4 + j;
#pragma unroll
            for (int h = 0; h < 2; h++) {
                int n   = rb * 128 + wm * 32 + i * 16 + g + h * 8;
                int col = cb * 128 + wn * 32 + j * 8 + 2 * tg;
                float v0 = f2tf_f(smax[t][h * 2 + 0]);
                float v1 = f2tf_f(smax[t][h * 2 + 1]);
                if (n == col)     v0 = 0.f;
                if (n == col + 1) v1 = 0.f;
                *(float2*)(g_s + (size_t)n * NN + col) = make_float2(v0, v1);
            }
        }
}

// ---------------- K3: rowsum + confi (int4 mask loads) ----------------------
__global__ void k_rowstats(const int* __restrict__ mask, float* __restrict__ confi_out) {
    int n = blockIdx.x;
    int tid = threadIdx.x;
    const float4* srow = (const float4*)(g_s + (size_t)n * NN);
    const int4* m4p = (const int4*)mask;
    float sum = 0.f, x0 = 0.f, x1 = 0.f, x2 = 0.f;
    for (int m4 = tid; m4 < NN / 4; m4 += 256) {
        float4 sv = srow[m4];
        int4 ma = m4p[m4 * 3 + 0];     // m0:v0 v1 v2 | m1:v0
        int4 mb = m4p[m4 * 3 + 1];     // m1:v1 v2 | m2:v0 v1
        int4 mc = m4p[m4 * 3 + 2];     // m2:v2 | m3:v0 v1 v2
        sum += (sv.x + sv.y) + (sv.z + sv.w);
        if (ma.x) x0 = fmaxf(x0, sv.x);
        if (ma.y) x1 = fmaxf(x1, sv.x);
        if (ma.z) x2 = fmaxf(x2, sv.x);
        if (ma.w) x0 = fmaxf(x0, sv.y);
        if (mb.x) x1 = fmaxf(x1, sv.y);
        if (mb.y) x2 = fmaxf(x2, sv.y);
        if (mb.z) x0 = fmaxf(x0, sv.z);
        if (mb.w) x1 = fmaxf(x1, sv.z);
        if (mc.x) x2 = fmaxf(x2, sv.z);
        if (mc.y) x0 = fmaxf(x0, sv.w);
        if (mc.z) x1 = fmaxf(x1, sv.w);
        if (mc.w) x2 = fmaxf(x2, sv.w);
    }
    __shared__ float rs0[256], rs1[256], rs2[256], rs3[256];
    rs0[tid] = sum; rs1[tid] = x0; rs2[tid] = x1; rs3[tid] = x2;
    __syncthreads();
    for (int off = 128; off > 0; off >>= 1) {
        if (tid < off) {
            rs0[tid] += rs0[tid + off];
            rs1[tid] = fmaxf(rs1[tid], rs1[tid + off]);
            rs2[tid] = fmaxf(rs2[tid], rs2[tid + off]);
            rs3[tid] = fmaxf(rs3[tid], rs3[tid + off]);
        }
        __syncthreads();
    }
    if (tid == 0) {
        g_rowsum[n] = rs0[0];
        confi_out[0 * NN + n] = fminf(fmaxf(0.2f * __logf(rs1[0] + 1e-9f), 0.f), 1.f);
        confi_out[1 * NN + n] = fminf(fmaxf(0.2f * __logf(rs2[0] + 1e-9f), 0.f), 1.f);
        confi_out[2 * NN + n] = fminf(fmaxf(0.2f * __logf(rs3[0] + 1e-9f), 0.f), 1.f);
    }
}

// ---------------- K4: new_x = (s/rowsum) @ xb_v -> blend -> Z ---------------
// Block 64 rows x 128 h, 256 threads, 8 warps 2x4, warp 32x32 -> 32 accum regs
// -> 2 blocks/SM (16 warps). grid (64, 2, 3) = 384 blocks.
#define NX_ABUF (64 * 36)
#define NX_BBUF (32 * 136)
__global__ __launch_bounds__(256, 2) void k_newx_tc(const int* __restrict__ mask,
                                                    float* __restrict__ out) {
    int rb = blockIdx.x, hb = blockIdx.y, v = blockIdx.z;
    int h0 = hb * 128;
    int tid = threadIdx.x, lane = tid & 31, wid = tid >> 5;
    int wm = wid >> 2, wn = wid & 3;
    int g = lane >> 2, tg = lane & 3;

    extern __shared__ float dyn[];
    float* Abuf = dyn;                       // [2][64*36]
    float* Bbuf = dyn + 2 * NX_ABUF;         // [2][32*136]
    __shared__ float yns[CC * 128];

    for (int l = tid; l < CC * 128; l += 256)
        yns[l] = g_yn[(l >> 7) * HH + h0 + (l & 127)];

    const float* xb = g_xb + (size_t)v * NN * HH;

    auto load_chunk = [&](int c, int buf) {
        int m0 = c * 32;
        float* Ab = Abuf + buf * NX_ABUF;
        float* Bb = Bbuf + buf * NX_BBUF;
#pragma unroll
        for (int q = 0; q < 2; q++) {            // A: 64x32 = 512 f4
            int l = q * 256 + tid;
            int r = l >> 3, kq = l & 7;
            cp16(Ab + r * 36 + kq * 4, g_s + (size_t)(rb * 64 + r) * NN + m0 + kq * 4);
        }
#pragma unroll
        for (int q = 0; q < 4; q++) {            // B: 32k x 128h = 1024 f4
            int l = q * 256 + tid;
            int kr = l >> 5, c4 = l & 31;
            cp16(Bb + kr * 136 + c4 * 4, xb + (size_t)(m0 + kr) * HH + h0 + c4 * 4);
        }
        CP_COMMIT();
    };

    float acc[8][4];
#pragma unroll
    for (int t = 0; t < 8; t++)
#pragma unroll
        for (int e = 0; e < 4; e++) acc[t][e] = 0.f;

    load_chunk(0, 0);

    for (int c = 0; c < NN / 32; c++) {
        CP_WAIT0();
        __syncthreads();
        if (c < NN / 32 - 1) load_chunk(c + 1, (c + 1) & 1);

        const float* As = Abuf + (c & 1) * NX_ABUF;
        const unsigned* Bs = (const unsigned*)(Bbuf + (c & 1) * NX_BBUF);
#pragma unroll
        for (int ks = 0; ks < 4; ks++) {
            unsigned a[2][4], b[4][2];
#pragma unroll
            for (int i = 0; i < 2; i++)
                ldsm4(a[i], As + (wm * 32 + i * 16 + (lane & 15)) * 36
                              + ks * 8 + ((lane >> 4) & 1) * 4);
#pragma unroll
            for (int j = 0; j < 4; j++) {
                int cc = wn * 32 + j * 8 + g;
                b[j][0] = Bs[(ks * 8 + tg) * 136 + cc];
                b[j][1] = Bs[(ks * 8 + tg + 4) * 136 + cc];
            }
#pragma unroll
            for (int i = 0; i < 2; i++)
#pragma unroll
                for (int j = 0; j < 4; j++)
                    mma_tf32(acc[i * 4 + j], a[i], b[j]);
        }
    }

    // epilogue: rowsum scale, mask blend, y_n expansion to Z
#pragma unroll
    for (int i = 0; i < 2; i++)
#pragma unroll
        for (int hh = 0; hh < 2; hh++) {
            int n = rb * 64 + wm * 32 + i * 16 + g + hh * 8;
            float rinv = 1.f / (g_rowsum[n] + 1e-9f);
            int mrow = mask[n * NV + v];
            float nx[8];
            if (mrow) {
                const float* xpr = g_xp + ((size_t)v * NN + n) * HH + h0;
#pragma unroll
                for (int j = 0; j < 4; j++) {
                    float2 p = *(const float2*)(xpr + wn * 32 + j * 8 + 2 * tg);
                    nx[j * 2] = p.x; nx[j * 2 + 1] = p.y;
                }
            } else {
#pragma unroll
                for (int j = 0; j < 4; j++) {
                    nx[j * 2]     = acc[i * 4 + j][hh * 2]     * rinv;
                    nx[j * 2 + 1] = acc[i * 4 + j][hh * 2 + 1] * rinv;
                }
            }
            size_t zbase = ((size_t)v * NN + n) * (CC * HH) + h0;
#pragma unroll
            for (int c = 0; c < CC; c++) {
#pragma unroll
                for (int j = 0; j < 4; j++) {
                    int col = wn * 32 + j * 8 + 2 * tg;
                    float2 yv = *(const float2*)&yns[c * 128 + col];
                    *(float2*)(out + zbase + (size_t)c * HH + col) =
                        make_float2(nx[j * 2] * yv.x, nx[j * 2 + 1] * yv.y);
                }
            }
        }
}

// ---------------- launch ----------------------------------------------------
extern "C" void kernel_launch(void* const* d_in, const int* in_sizes, int n_in,
                              void* d_out, int out_size) {
    ProjPtrs P{};
    RoundPtrs R{};
    const float* yv  = nullptr;
    const float* Wy  = nullptr;
    const float* byp = nullptr;
    const int*   mask = nullptr;
    int nx = 0, nW = 0, nb = 0;
    for (int i = 0; i < n_in; i++) {
        int s = in_sizes[i];
        if      (s == NN * DD)  { if (nx < NV) R.x[nx++] = (const float*)d_in[i]; }
        else if (s == HH * DD)  { if (nW < NV) R.W[nW++] = (const float*)d_in[i]; }
        else if (s == CC * DYY) yv = (const float*)d_in[i];
        else if (s == HH * DYY) Wy = (const float*)d_in[i];
        else if (s == NN * NV)  mask = (const int*)d_in[i];
        else if (s == HH) {
            if (nb < NV) P.b[nb++] = (const float*)d_in[i];
            else         byp = (const float*)d_in[i];
        }
    }
    P.mask = mask;
    float* out = (float*)d_out;
    float* confi_out = out + ((size_t)out_size - (size_t)NV * NN);

    const int proj_dyn = 2 * (PROJ_ABUF + PROJ_BBUF) * (int)sizeof(float);  // 110592
    const int smat_dyn = 4 * SMAT_BUF * (int)sizeof(float);                 // 73728
    const int newx_dyn = 2 * (NX_ABUF + NX_BBUF) * (int)sizeof(float);      // 53248
    cudaFuncSetAttribute(k_proj_tc, cudaFuncAttributeMaxDynamicSharedMemorySize, proj_dyn);
    cudaFuncSetAttribute(k_smat_tc, cudaFuncAttributeMaxDynamicSharedMemorySize, smat_dyn);
    cudaFuncSetAttribute(k_newx_tc, cudaFuncAttributeMaxDynamicSharedMemorySize, newx_dyn);

    int round_total = 3 * (NN * DD / 4) + 3 * (HH * DD / 4);
    k_round   <<<(round_total + 255) / 256, 256>>>(R);
    k_yn      <<<CC, HH>>>(yv, Wy, byp);
    k_proj_tc <<<dim3(NN / 128, NV), 512, proj_dyn>>>(P);
    k_smat_tc <<<dim3(NN / 128, NN / 128), 512, smat_dyn>>>(mask);
    k_rowstats<<<NN, 256>>>(mask, confi_out);
    k_newx_tc <<<dim3(NN / 64, HH / 128, NV), 256, newx_dyn>>>(mask, out);
}

// round 16
// speedup vs baseline: 1.0062x; 1.0062x over previous
#include <cuda_runtime.h>
#include <cuda_bf16.h>

#define NV  3
#define NN  4096
#define HH  256
#define CC  20
#define DYY 300
#define DD  512

// ---------------- scratch (static device globals) ---------------------------
__device__ float g_xp[(size_t)NV * NN * HH];   // leaky(x@W^T+b)  (fp32)
__device__ float g_xq[(size_t)NV * NN * HH];   // normalized, tf32-rounded
__device__ float g_xb[(size_t)NV * NN * HH];   // xp*colmask, tf32-rounded
__device__ float g_xbT[(size_t)NV * HH * NN];  // xb transposed [v][h][n]
__device__ float g_s [(size_t)NN * NN];        // max_v exp(...), tf32-rounded
__device__ float g_rowsum[NN];
__device__ float g_yn[CC * HH];
__device__ float g_xr[(size_t)NV * NN * DD];   // x rounded to tf32
__device__ float g_wr[(size_t)NV * HH * DD];   // W rounded to tf32

struct ProjPtrs {
    const float* b[NV];
    const int*   mask;
};
struct RoundPtrs {
    const float* x[NV];
    const float* W[NV];
};

// ---------------- helpers ---------------------------------------------------
__device__ __forceinline__ unsigned f2tf(float f) {
    unsigned u;
    asm("cvt.rna.tf32.f32 %0, %1;" : "=r"(u) : "f"(f));
    return u;
}
__device__ __forceinline__ float f2tf_f(float f) { return __uint_as_float(f2tf(f)); }

__device__ __forceinline__ void mma_tf32(float* d, const unsigned* a, const unsigned* b) {
    asm volatile(
        "mma.sync.aligned.m16n8k8.row.col.f32.tf32.tf32.f32 "
        "{%0,%1,%2,%3},{%4,%5,%6,%7},{%8,%9},{%0,%1,%2,%3};"
        : "+f"(d[0]), "+f"(d[1]), "+f"(d[2]), "+f"(d[3])
        : "r"(a[0]), "r"(a[1]), "r"(a[2]), "r"(a[3]), "r"(b[0]), "r"(b[1]));
}

__device__ __forceinline__ void ldsm4(unsigned* r, const void* p) {
    unsigned a = (unsigned)__cvta_generic_to_shared(p);
    asm volatile("ldmatrix.sync.aligned.m8n8.x4.shared.b16 {%0,%1,%2,%3}, [%4];"
                 : "=r"(r[0]), "=r"(r[1]), "=r"(r[2]), "=r"(r[3]) : "r"(a));
}

__device__ __forceinline__ void cp16(float* dst, const float* src) {
    unsigned d = (unsigned)__cvta_generic_to_shared(dst);
    asm volatile("cp.async.cg.shared.global [%0], [%1], 16;" :: "r"(d), "l"(src) : "memory");
}
#define CP_COMMIT() asm volatile("cp.async.commit_group;" ::: "memory")
#define CP_WAIT0()  asm volatile("cp.async.wait_group 0;" ::: "memory")

// ---------------- K-1: round x, W to tf32 in gmem ---------------------------
__global__ void k_round(RoundPtrs R) {
    const int XN4 = NN * DD / 4, WN4 = HH * DD / 4;
    int idx = blockIdx.x * 256 + threadIdx.x;
    float4 f;
    float* dst;
    if (idx < 3 * XN4) {
        int v = idx / XN4, r = idx % XN4;
        f = ((const float4*)R.x[v])[r];
        dst = g_xr + (size_t)v * NN * DD + (size_t)r * 4;
    } else if (idx < 3 * XN4 + 3 * WN4) {
        int t = idx - 3 * XN4;
        int v = t / WN4, r = t % WN4;
        f = ((const float4*)R.W[v])[r];
        dst = g_wr + (size_t)v * HH * DD + (size_t)r * 4;
    } else return;
    f.x = f2tf_f(f.x); f.y = f2tf_f(f.y); f.z = f2tf_f(f.z); f.w = f2tf_f(f.w);
    *(float4*)dst = f;
}

// ---------------- K0: y_n = sigmoid(y @ Wy^T + by) --------------------------
__global__ void k_yn(const float* __restrict__ y,
                     const float* __restrict__ Wy,
                     const float* __restrict__ by) {
    int c = blockIdx.x;
    int h = threadIdx.x;
    __shared__ float ys[DYY];
    for (int d = threadIdx.x; d < DYY; d += blockDim.x) ys[d] = y[c * DYY + d];
    __syncthreads();
    const float* wr = Wy + (size_t)h * DYY;
    float acc = 0.f;
#pragma unroll 4
    for (int d = 0; d < DYY; d++) acc = fmaf(ys[d], wr[d], acc);
    acc += by[h];
    g_yn[c * HH + h] = 1.f / (1.f + __expf(-acc));
}

// ---------------- K1: tensor-core proj: xp / xq / xb ------------------------
#define PROJ_ABUF (128 * 36)
#define PROJ_BBUF (256 * 36)
__global__ __launch_bounds__(512, 1) void k_proj_tc(ProjPtrs P) {
    int v = blockIdx.y, rb = blockIdx.x;
    int tid = threadIdx.x, lane = tid & 31, wid = tid >> 5;
    int wm = wid >> 2, wn = wid & 3;
    int g = lane >> 2, tg = lane & 3;

    extern __shared__ float dyn[];
    float* Abuf = dyn;
    float* Bbuf = dyn + 2 * PROJ_ABUF;
    __shared__ float ss[4][128];

    const float* xr = g_xr + (size_t)v * NN * DD;
    const float* wr = g_wr + (size_t)v * HH * DD;

    auto load_chunk = [&](int c, int buf) {
        int k0 = c * 32;
        float* A = Abuf + buf * PROJ_ABUF;
        float* B = Bbuf + buf * PROJ_BBUF;
#pragma unroll
        for (int q = 0; q < 2; q++) {
            int l = q * 512 + tid;
            int r = l >> 3, kq = l & 7;
            cp16(A + r * 36 + kq * 4, xr + (size_t)(rb * 128 + r) * DD + k0 + kq * 4);
        }
#pragma unroll
        for (int q = 0; q < 4; q++) {
            int l = q * 512 + tid;
            int r = l >> 3, kq = l & 7;
            cp16(B + r * 36 + kq * 4, wr + (size_t)r * DD + k0 + kq * 4);
        }
        CP_COMMIT();
    };

    float acc[16][4];
#pragma unroll
    for (int t = 0; t < 16; t++)
#pragma unroll
        for (int e = 0; e < 4; e++) acc[t][e] = 0.f;

    load_chunk(0, 0);
    for (int c = 0; c < DD / 32; c++) {
        CP_WAIT0();
        __syncthreads();
        if (c < DD / 32 - 1) load_chunk(c + 1, (c + 1) & 1);
        const float* A = Abuf + (c & 1) * PROJ_ABUF;
        const float* B = Bbuf + (c & 1) * PROJ_BBUF;
#pragma unroll
        for (int ks = 0; ks < 4; ks++) {
            unsigned a[2][4], b[8][2];
#pragma unroll
            for (int i = 0; i < 2; i++)
                ldsm4(a[i], A + (wm * 32 + i * 16 + (lane & 15)) * 36
                              + ks * 8 + ((lane >> 4) & 1) * 4);
#pragma unroll
            for (int jp = 0; jp < 4; jp++) {
                unsigned t[4];
                ldsm4(t, B + (wn * 64 + jp * 16 + (lane & 7) + ((lane >> 4) & 1) * 8) * 36
                           + ks * 8 + ((lane >> 3) & 1) * 4);
                b[jp * 2][0] = t[0]; b[jp * 2][1] = t[1];
                b[jp * 2 + 1][0] = t[2]; b[jp * 2 + 1][1] = t[3];
            }
#pragma unroll
            for (int i = 0; i < 2; i++)
#pragma unroll
                for (int j = 0; j < 8; j++)
                    mma_tf32(acc[i * 8 + j], a[i], b[j]);
        }
    }

    float bcol[16];
#pragma unroll
    for (int j = 0; j < 8; j++) {
        bcol[j * 2]     = P.b[v][wn * 64 + j * 8 + 2 * tg];
        bcol[j * 2 + 1] = P.b[v][wn * 64 + j * 8 + 2 * tg + 1];
    }
    float ssq[4];
#pragma unroll
    for (int i = 0; i < 2; i++)
#pragma unroll
        for (int hh = 0; hh < 2; hh++) {
            float s = 0.f;
#pragma unroll
            for (int j = 0; j < 8; j++)
#pragma unroll
                for (int e = 0; e < 2; e++) {
                    float t = acc[i * 8 + j][hh * 2 + e] + bcol[j * 2 + e];
                    t = (t >= 0.f) ? t : 0.1f * t;
                    acc[i * 8 + j][hh * 2 + e] = t;
                    s = fmaf(t, t, s);
                }
            ssq[i * 2 + hh] = s;
        }
#pragma unroll
    for (int r4 = 0; r4 < 4; r4++) {
        ssq[r4] += __shfl_xor_sync(0xFFFFFFFFu, ssq[r4], 1);
        ssq[r4] += __shfl_xor_sync(0xFFFFFFFFu, ssq[r4], 2);
    }
    if (tg == 0) {
#pragma unroll
        for (int i = 0; i < 2; i++)
#pragma unroll
            for (int hh = 0; hh < 2; hh++)
                ss[wn][wm * 32 + i * 16 + hh * 8 + g] = ssq[i * 2 + hh];
    }
    __syncthreads();
#pragma unroll
    for (int i = 0; i < 2; i++)
#pragma unroll
        for (int hh = 0; hh < 2; hh++) {
            int lr = wm * 32 + i * 16 + hh * 8 + g;
            int n = rb * 128 + lr;
            float tot = (ss[0][lr] + ss[1][lr]) + (ss[2][lr] + ss[3][lr]);
            float rinv = 1.f / fmaxf(sqrtf(tot), 1e-12f);
            float mrow = (float)P.mask[n * NV + v];
            size_t base = ((size_t)v * NN + n) * HH;
#pragma unroll
            for (int j = 0; j < 8; j++) {
                int col = wn * 64 + j * 8 + 2 * tg;
                float p0 = acc[i * 8 + j][hh * 2];
                float p1 = acc[i * 8 + j][hh * 2 + 1];
                *(float2*)(g_xp + base + col) = make_float2(p0, p1);
                *(float2*)(g_xq + base + col) =
                    make_float2(f2tf_f(p0 * rinv), f2tf_f(p1 * rinv));
                *(float2*)(g_xb + base + col) =
                    make_float2(f2tf_f(p0 * mrow), f2tf_f(p1 * mrow));
            }
        }
}

// ---------------- K1b: transpose xb -> xbT [v][h][n] -----------------------
__global__ void k_xbt() {
    int v = blockIdx.z;
    int nb = blockIdx.x, hb = blockIdx.y;
    __shared__ float t[32][33];
    int tx = threadIdx.x & 31, ty = threadIdx.x >> 5;
    const float* src = g_xb + (size_t)v * NN * HH;
    float* dst = g_xbT + (size_t)v * HH * NN;
#pragma unroll
    for (int i = 0; i < 4; i++)
        t[ty + 8 * i][tx] = src[(size_t)(nb * 32 + ty + 8 * i) * HH + hb * 32 + tx];
    __syncthreads();
#pragma unroll
    for (int i = 0; i < 4; i++)
        dst[(size_t)(hb * 32 + ty + 8 * i) * NN + nb * 32 + tx] = t[tx][ty + 8 * i];
}

// ---------------- K2: s (SYMMETRIC: upper-triangular blocks only) -----------
// 528 blocks (rb <= cb); off-diagonal tiles also written transposed via smem.
#define SMAT_BUF (128 * 36)
__global__ __launch_bounds__(512, 1) void k_smat_tc(const int* __restrict__ mask) {
    int rem = blockIdx.x, rb = 0;
    while (rem >= 32 - rb) { rem -= 32 - rb; rb++; }
    int cb = rb + rem;

    int tid = threadIdx.x, lane = tid & 31, wid = tid >> 5;
    int wm = wid >> 2, wn = wid & 3;
    int g = lane >> 2, tg = lane & 3;

    extern __shared__ float dyn[];
    float* Abuf = dyn;
    float* Bbuf = dyn + 2 * SMAT_BUF;

    __shared__ int rm_s[NV][128], cm_s[NV][128];
    for (int l = tid; l < 128; l += 512) {
#pragma unroll
        for (int v = 0; v < NV; v++) {
            rm_s[v][l] = mask[(rb * 128 + l) * NV + v];
            cm_s[v][l] = mask[(cb * 128 + l) * NV + v];
        }
    }

    auto load_chunk = [&](int c, int buf) {
        int v = c >> 3, k0 = (c & 7) * 32;
        const float* xq = g_xq + (size_t)v * NN * HH;
        float* Ab = Abuf + buf * SMAT_BUF;
        float* Bb = Bbuf + buf * SMAT_BUF;
#pragma unroll
        for (int q = 0; q < 2; q++) {
            int l = q * 512 + tid;
            int r = l >> 3, kq = l & 7;
            cp16(Ab + r * 36 + kq * 4, xq + (size_t)(rb * 128 + r) * HH + k0 + kq * 4);
            cp16(Bb + r * 36 + kq * 4, xq + (size_t)(cb * 128 + r) * HH + k0 + kq * 4);
        }
        CP_COMMIT();
    };

    float smax[8][4], dot[8][4];
#pragma unroll
    for (int t = 0; t < 8; t++)
#pragma unroll
        for (int e = 0; e < 4; e++) { smax[t][e] = 0.f; dot[t][e] = 0.f; }

    load_chunk(0, 0);

    for (int c = 0; c < 24; c++) {
        CP_WAIT0();
        __syncthreads();
        if (c < 23) load_chunk(c + 1, (c + 1) & 1);

        const float* As = Abuf + (c & 1) * SMAT_BUF;
        const float* Bs = Bbuf + (c & 1) * SMAT_BUF;
#pragma unroll
        for (int ks = 0; ks < 4; ks++) {
            unsigned a[2][4], b[4][2];
#pragma unroll
            for (int i = 0; i < 2; i++)
                ldsm4(a[i], As + (wm * 32 + i * 16 + (lane & 15)) * 36
                              + ks * 8 + ((lane >> 4) & 1) * 4);
#pragma unroll
            for (int jp = 0; jp < 2; jp++) {
                unsigned t[4];
                ldsm4(t, Bs + (wn * 32 + jp * 16 + (lane & 7) + ((lane >> 4) & 1) * 8) * 36
                           + ks * 8 + ((lane >> 3) & 1) * 4);
                b[jp * 2][0] = t[0]; b[jp * 2][1] = t[1];
                b[jp * 2 + 1][0] = t[2]; b[jp * 2 + 1][1] = t[3];
            }
#pragma unroll
            for (int i = 0; i < 2; i++)
#pragma unroll
                for (int j = 0; j < 4; j++)
                    mma_tf32(dot[i * 4 + j], a[i], b[j]);
        }

        if ((c & 7) == 7) {
            int v = c >> 3;
#pragma unroll
            for (int i = 0; i < 2; i++)
#pragma unroll
                for (int j = 0; j < 4; j++) {
                    int t = i * 4 + j;
#pragma unroll
                    for (int e = 0; e < 4; e++) {
                        int rl = wm * 32 + i * 16 + g + ((e >> 1) << 3);
                        int cl = wn * 32 + j * 8 + 2 * tg + (e & 1);
                        if (rm_s[v][rl] && cm_s[v][cl])
                            smax[t][e] = fmaxf(smax[t][e], __expf(dot[t][e] * 5.0f));
                        dot[t][e] = 0.f;
                    }
                }
        }
    }

    // store: direct tile always; off-diagonal also staged transposed in smem
    bool offdiag = (rb != cb);
    float* tile = dyn;                 // reuse pipeline buffers: 128 x 132
    __syncthreads();                   // all reads of dyn are done

#pragma unroll
    for (int i = 0; i < 2; i++)
#pragma unroll
        for (int j = 0; j < 4; j++) {
            int t = i * 4 + j;
#pragma unroll
            for (int h = 0; h < 2; h++) {
                int rl  = wm * 32 + i * 16 + g + h * 8;
                int cl  = wn * 32 + j * 8 + 2 * tg;
                int n   = rb * 128 + rl;
                int col = cb * 128 + cl;
                float v0 = f2tf_f(smax[t][h * 2 + 0]);
                float v1 = f2tf_f(smax[t][h * 2 + 1]);
                if (n == col)     v0 = 0.f;
                if (n == col + 1) v1 = 0.f;
                *(float2*)(g_s + (size_t)n * NN + col) = make_float2(v0, v1);
                if (offdiag) {
                    tile[cl * 132 + rl]       = v0;
                    tile[(cl + 1) * 132 + rl] = v1;
                }
            }
        }

    if (offdiag) {
        __syncthreads();
#pragma unroll
        for (int q = 0; q < 8; q++) {          // 128 rows x 32 float4
            int l = q * 512 + tid;
            int r = l >> 5, c4 = l & 31;
            float4 f = *(const float4*)&tile[r * 132 + c4 * 4];
            *(float4*)(g_s + (size_t)(cb * 128 + r) * NN + rb * 128 + c4 * 4) = f;
        }
    }
}

// ---------------- K3: rowsum + confi (int4 mask loads) ----------------------
__global__ void k_rowstats(const int* __restrict__ mask, float* __restrict__ confi_out) {
    int n = blockIdx.x;
    int tid = threadIdx.x;
    const float4* srow = (const float4*)(g_s + (size_t)n * NN);
    const int4* m4p = (const int4*)mask;
    float sum = 0.f, x0 = 0.f, x1 = 0.f, x2 = 0.f;
    for (int m4 = tid; m4 < NN / 4; m4 += 256) {
        float4 sv = srow[m4];
        int4 ma = m4p[m4 * 3 + 0];
        int4 mb = m4p[m4 * 3 + 1];
        int4 mc = m4p[m4 * 3 + 2];
        sum += (sv.x + sv.y) + (sv.z + sv.w);
        if (ma.x) x0 = fmaxf(x0, sv.x);
        if (ma.y) x1 = fmaxf(x1, sv.x);
        if (ma.z) x2 = fmaxf(x2, sv.x);
        if (ma.w) x0 = fmaxf(x0, sv.y);
        if (mb.x) x1 = fmaxf(x1, sv.y);
        if (mb.y) x2 = fmaxf(x2, sv.y);
        if (mb.z) x0 = fmaxf(x0, sv.z);
        if (mb.w) x1 = fmaxf(x1, sv.z);
        if (mc.x) x2 = fmaxf(x2, sv.z);
        if (mc.y) x0 = fmaxf(x0, sv.w);
        if (mc.z) x1 = fmaxf(x1, sv.w);
        if (mc.w) x2 = fmaxf(x2, sv.w);
    }
    __shared__ float rs0[256], rs1[256], rs2[256], rs3[256];
    rs0[tid] = sum; rs1[tid] = x0; rs2[tid] = x1; rs3[tid] = x2;
    __syncthreads();
    for (int off = 128; off > 0; off >>= 1) {
        if (tid < off) {
            rs0[tid] += rs0[tid + off];
            rs1[tid] = fmaxf(rs1[tid], rs1[tid + off]);
            rs2[tid] = fmaxf(rs2[tid], rs2[tid + off]);
            rs3[tid] = fmaxf(rs3[tid], rs3[tid + off]);
        }
        __syncthreads();
    }
    if (tid == 0) {
        g_rowsum[n] = rs0[0];
        confi_out[0 * NN + n] = fminf(fmaxf(0.2f * __logf(rs1[0] + 1e-9f), 0.f), 1.f);
        confi_out[1 * NN + n] = fminf(fmaxf(0.2f * __logf(rs2[0] + 1e-9f), 0.f), 1.f);
        confi_out[2 * NN + n] = fminf(fmaxf(0.2f * __logf(rs3[0] + 1e-9f), 0.f), 1.f);
    }
}

// ---------------- K4: new_x = (s/rowsum) @ xb_v -> blend -> Z ---------------
// Block 64 rows x 128 h, 8 warps 2x4, warp 32x32, 2 blocks/SM.
// B now loaded from g_xbT [h][n] -> ldmatrix path (no scalar LDS stream).
#define NX_ABUF (64 * 36)
#define NX_BBUF (128 * 36)
__global__ __launch_bounds__(256, 2) void k_newx_tc(const int* __restrict__ mask,
                                                    float* __restrict__ out) {
    int rb = blockIdx.x, hb = blockIdx.y, v = blockIdx.z;
    int h0 = hb * 128;
    int tid = threadIdx.x, lane = tid & 31, wid = tid >> 5;
    int wm = wid >> 2, wn = wid & 3;
    int g = lane >> 2, tg = lane & 3;

    extern __shared__ float dyn[];
    float* Abuf = dyn;                       // [2][64*36]
    float* Bbuf = dyn + 2 * NX_ABUF;         // [2][128*36]
    __shared__ float yns[CC * 128];

    for (int l = tid; l < CC * 128; l += 256)
        yns[l] = g_yn[(l >> 7) * HH + h0 + (l & 127)];

    const float* xbT = g_xbT + (size_t)v * HH * NN;

    auto load_chunk = [&](int c, int buf) {
        int m0 = c * 32;
        float* Ab = Abuf + buf * NX_ABUF;
        float* Bb = Bbuf + buf * NX_BBUF;
#pragma unroll
        for (int q = 0; q < 2; q++) {            // A: 64 x 32
            int l = q * 256 + tid;
            int r = l >> 3, kq = l & 7;
            cp16(Ab + r * 36 + kq * 4, g_s + (size_t)(rb * 64 + r) * NN + m0 + kq * 4);
        }
#pragma unroll
        for (int q = 0; q < 4; q++) {            // B: 128 h-rows x 32 k
            int l = q * 256 + tid;
            int r = l >> 3, kq = l & 7;
            cp16(Bb + r * 36 + kq * 4, xbT + (size_t)(h0 + r) * NN + m0 + kq * 4);
        }
        CP_COMMIT();
    };

    float acc[8][4];
#pragma unroll
    for (int t = 0; t < 8; t++)
#pragma unroll
        for (int e = 0; e < 4; e++) acc[t][e] = 0.f;

    load_chunk(0, 0);

    for (int c = 0; c < NN / 32; c++) {
        CP_WAIT0();
        __syncthreads();
        if (c < NN / 32 - 1) load_chunk(c + 1, (c + 1) & 1);

        const float* As = Abuf + (c & 1) * NX_ABUF;
        const float* Bs = Bbuf + (c & 1) * NX_BBUF;
#pragma unroll
        for (int ks = 0; ks < 4; ks++) {
            unsigned a[2][4], b[4][2];
#pragma unroll
            for (int i = 0; i < 2; i++)
                ldsm4(a[i], As + (wm * 32 + i * 16 + (lane & 15)) * 36
                              + ks * 8 + ((lane >> 4) & 1) * 4);
#pragma unroll
            for (int jp = 0; jp < 2; jp++) {
                unsigned t[4];
                ldsm4(t, Bs + (wn * 32 + jp * 16 + (lane & 7) + ((lane >> 4) & 1) * 8) * 36
                           + ks * 8 + ((lane >> 3) & 1) * 4);
                b[jp * 2][0] = t[0]; b[jp * 2][1] = t[1];
                b[jp * 2 + 1][0] = t[2]; b[jp * 2 + 1][1] = t[3];
            }
#pragma unroll
            for (int i = 0; i < 2; i++)
#pragma unroll
                for (int j = 0; j < 4; j++)
                    mma_tf32(acc[i * 4 + j], a[i], b[j]);
        }
    }

    // epilogue: rowsum scale, mask blend, y_n expansion to Z
#pragma unroll
    for (int i = 0; i < 2; i++)
#pragma unroll
        for (int hh = 0; hh < 2; hh++) {
            int n = rb * 64 + wm * 32 + i * 16 + g + hh * 8;
            float rinv = 1.f / (g_rowsum[n] + 1e-9f);
            int mrow = mask[n * NV + v];
            float nx[8];
            if (mrow) {
                const float* xpr = g_xp + ((size_t)v * NN + n) * HH + h0;
#pragma unroll
                for (int j = 0; j < 4; j++) {
                    float2 p = *(const float2*)(xpr + wn * 32 + j * 8 + 2 * tg);
                    nx[j * 2] = p.x; nx[j * 2 + 1] = p.y;
                }
            } else {
#pragma unroll
                for (int j = 0; j < 4; j++) {
                    nx[j * 2]     = acc[i * 4 + j][hh * 2]     * rinv;
                    nx[j * 2 + 1] = acc[i * 4 + j][hh * 2 + 1] * rinv;
                }
            }
            size_t zbase = ((size_t)v * NN + n) * (CC * HH) + h0;
#pragma unroll
            for (int c = 0; c < CC; c++) {
#pragma unroll
                for (int j = 0; j < 4; j++) {
                    int col = wn * 32 + j * 8 + 2 * tg;
                    float2 yv = *(const float2*)&yns[c * 128 + col];
                    *(float2*)(out + zbase + (size_t)c * HH + col) =
                        make_float2(nx[j * 2] * yv.x, nx[j * 2 + 1] * yv.y);
                }
            }
        }
}

// ---------------- launch ----------------------------------------------------
extern "C" void kernel_launch(void* const* d_in, const int* in_sizes, int n_in,
                              void* d_out, int out_size) {
    ProjPtrs P{};
    RoundPtrs R{};
    const float* yv  = nullptr;
    const float* Wy  = nullptr;
    const float* byp = nullptr;
    const int*   mask = nullptr;
    int nx = 0, nW = 0, nb = 0;
    for (int i = 0; i < n_in; i++) {
        int s = in_sizes[i];
        if      (s == NN * DD)  { if (nx < NV) R.x[nx++] = (const float*)d_in[i]; }
        else if (s == HH * DD)  { if (nW < NV) R.W[nW++] = (const float*)d_in[i]; }
        else if (s == CC * DYY) yv = (const float*)d_in[i];
        else if (s == HH * DYY) Wy = (const float*)d_in[i];
        else if (s == NN * NV)  mask = (const int*)d_in[i];
        else if (s == HH) {
            if (nb < NV) P.b[nb++] = (const float*)d_in[i];
            else         byp = (const float*)d_in[i];
        }
    }
    P.mask = mask;
    float* out = (float*)d_out;
    float* confi_out = out + ((size_t)out_size - (size_t)NV * NN);

    const int proj_dyn = 2 * (PROJ_ABUF + PROJ_BBUF) * (int)sizeof(float);  // 110592
    const int smat_dyn = 4 * SMAT_BUF * (int)sizeof(float);                 // 73728
    const int newx_dyn = 2 * (NX_ABUF + NX_BBUF) * (int)sizeof(float);      // 55296
    cudaFuncSetAttribute(k_proj_tc, cudaFuncAttributeMaxDynamicSharedMemorySize, proj_dyn);
    cudaFuncSetAttribute(k_smat_tc, cudaFuncAttributeMaxDynamicSharedMemorySize, smat_dyn);
    cudaFuncSetAttribute(k_newx_tc, cudaFuncAttributeMaxDynamicSharedMemorySize, newx_dyn);

    int round_total = 3 * (NN * DD / 4) + 3 * (HH * DD / 4);
    k_round   <<<(round_total + 255) / 256, 256>>>(R);
    k_yn      <<<CC, HH>>>(yv, Wy, byp);
    k_proj_tc <<<dim3(NN / 128, NV), 512, proj_dyn>>>(P);
    k_xbt     <<<dim3(NN / 32, HH / 32, NV), 256>>>();
    k_smat_tc <<<528, 512, smat_dyn>>>(mask);
    k_rowstats<<<NN, 256>>>(mask, confi_out);
    k_newx_tc <<<dim3(NN / 64, HH / 128, NV), 256, newx_dyn>>>(mask, out);
}

// round 17
// speedup vs baseline: 1.2446x; 1.2370x over previous
#include <cuda_runtime.h>
#include <cuda_bf16.h>

#define NV  3
#define NN  4096
#define HH  256
#define CC  20
#define DYY 300
#define DD  512

// ---------------- scratch (static device globals) ---------------------------
__device__ float g_xp[(size_t)NV * NN * HH];   // leaky(x@W^T+b)  (fp32)
__device__ float g_xq[(size_t)NV * NN * HH];   // normalized, tf32-rounded
__device__ float g_xb[(size_t)NV * NN * HH];   // xp*colmask, tf32-rounded
__device__ float g_s [(size_t)NN * NN];        // max_v exp(...), tf32-rounded
__device__ float g_rowsum[NN];
__device__ float g_yn[CC * HH];
__device__ float g_xr[(size_t)NV * NN * DD];   // x rounded to tf32
__device__ float g_wr[(size_t)NV * HH * DD];   // W rounded to tf32

struct ProjPtrs {
    const float* b[NV];
    const int*   mask;
};
struct RoundPtrs {
    const float* x[NV];
    const float* W[NV];
};

// ---------------- helpers ---------------------------------------------------
__device__ __forceinline__ unsigned f2tf(float f) {
    unsigned u;
    asm("cvt.rna.tf32.f32 %0, %1;" : "=r"(u) : "f"(f));
    return u;
}
__device__ __forceinline__ float f2tf_f(float f) { return __uint_as_float(f2tf(f)); }

__device__ __forceinline__ void mma_tf32(float* d, const unsigned* a, const unsigned* b) {
    asm volatile(
        "mma.sync.aligned.m16n8k8.row.col.f32.tf32.tf32.f32 "
        "{%0,%1,%2,%3},{%4,%5,%6,%7},{%8,%9},{%0,%1,%2,%3};"
        : "+f"(d[0]), "+f"(d[1]), "+f"(d[2]), "+f"(d[3])
        : "r"(a[0]), "r"(a[1]), "r"(a[2]), "r"(a[3]), "r"(b[0]), "r"(b[1]));
}

__device__ __forceinline__ void ldsm4(unsigned* r, const void* p) {
    unsigned a = (unsigned)__cvta_generic_to_shared(p);
    asm volatile("ldmatrix.sync.aligned.m8n8.x4.shared.b16 {%0,%1,%2,%3}, [%4];"
                 : "=r"(r[0]), "=r"(r[1]), "=r"(r[2]), "=r"(r[3]) : "r"(a));
}

__device__ __forceinline__ void cp16(float* dst, const float* src) {
    unsigned d = (unsigned)__cvta_generic_to_shared(dst);
    asm volatile("cp.async.cg.shared.global [%0], [%1], 16;" :: "r"(d), "l"(src) : "memory");
}
#define CP_COMMIT() asm volatile("cp.async.commit_group;" ::: "memory")
#define CP_WAIT0()  asm volatile("cp.async.wait_group 0;" ::: "memory")
#define CP_WAIT1()  asm volatile("cp.async.wait_group 1;" ::: "memory")

// ---------------- K-1: round x, W to tf32 in gmem ---------------------------
__global__ void k_round(RoundPtrs R) {
    const int XN4 = NN * DD / 4, WN4 = HH * DD / 4;
    int idx = blockIdx.x * 256 + threadIdx.x;
    float4 f;
    float* dst;
    if (idx < 3 * XN4) {
        int v = idx / XN4, r = idx % XN4;
        f = ((const float4*)R.x[v])[r];
        dst = g_xr + (size_t)v * NN * DD + (size_t)r * 4;
    } else if (idx < 3 * XN4 + 3 * WN4) {
        int t = idx - 3 * XN4;
        int v = t / WN4, r = t % WN4;
        f = ((const float4*)R.W[v])[r];
        dst = g_wr + (size_t)v * HH * DD + (size_t)r * 4;
    } else return;
    f.x = f2tf_f(f.x); f.y = f2tf_f(f.y); f.z = f2tf_f(f.z); f.w = f2tf_f(f.w);
    *(float4*)dst = f;
}

// ---------------- K0: y_n = sigmoid(y @ Wy^T + by) --------------------------
__global__ void k_yn(const float* __restrict__ y,
                     const float* __restrict__ Wy,
                     const float* __restrict__ by) {
    int c = blockIdx.x;
    int h = threadIdx.x;
    __shared__ float ys[DYY];
    for (int d = threadIdx.x; d < DYY; d += blockDim.x) ys[d] = y[c * DYY + d];
    __syncthreads();
    const float* wr = Wy + (size_t)h * DYY;
    float acc = 0.f;
#pragma unroll 4
    for (int d = 0; d < DYY; d++) acc = fmaf(ys[d], wr[d], acc);
    acc += by[h];
    g_yn[c * HH + h] = 1.f / (1.f + __expf(-acc));
}

// ---------------- K1: tensor-core proj: xp / xq / xb ------------------------
#define PROJ_ABUF (128 * 36)
#define PROJ_BBUF (256 * 36)
__global__ __launch_bounds__(512, 1) void k_proj_tc(ProjPtrs P) {
    int v = blockIdx.y, rb = blockIdx.x;
    int tid = threadIdx.x, lane = tid & 31, wid = tid >> 5;
    int wm = wid >> 2, wn = wid & 3;
    int g = lane >> 2, tg = lane & 3;

    extern __shared__ float dyn[];
    float* Abuf = dyn;
    float* Bbuf = dyn + 2 * PROJ_ABUF;
    __shared__ float ss[4][128];

    const float* xr = g_xr + (size_t)v * NN * DD;
    const float* wr = g_wr + (size_t)v * HH * DD;

    auto load_chunk = [&](int c, int buf) {
        int k0 = c * 32;
        float* A = Abuf + buf * PROJ_ABUF;
        float* B = Bbuf + buf * PROJ_BBUF;
#pragma unroll
        for (int q = 0; q < 2; q++) {
            int l = q * 512 + tid;
            int r = l >> 3, kq = l & 7;
            cp16(A + r * 36 + kq * 4, xr + (size_t)(rb * 128 + r) * DD + k0 + kq * 4);
        }
#pragma unroll
        for (int q = 0; q < 4; q++) {
            int l = q * 512 + tid;
            int r = l >> 3, kq = l & 7;
            cp16(B + r * 36 + kq * 4, wr + (size_t)r * DD + k0 + kq * 4);
        }
        CP_COMMIT();
    };

    float acc[16][4];
#pragma unroll
    for (int t = 0; t < 16; t++)
#pragma unroll
        for (int e = 0; e < 4; e++) acc[t][e] = 0.f;

    load_chunk(0, 0);
    for (int c = 0; c < DD / 32; c++) {
        CP_WAIT0();
        __syncthreads();
        if (c < DD / 32 - 1) load_chunk(c + 1, (c + 1) & 1);
        const float* A = Abuf + (c & 1) * PROJ_ABUF;
        const float* B = Bbuf + (c & 1) * PROJ_BBUF;
#pragma unroll
        for (int ks = 0; ks < 4; ks++) {
            unsigned a[2][4], b[8][2];
#pragma unroll
            for (int i = 0; i < 2; i++)
                ldsm4(a[i], A + (wm * 32 + i * 16 + (lane & 15)) * 36
                              + ks * 8 + ((lane >> 4) & 1) * 4);
#pragma unroll
            for (int jp = 0; jp < 4; jp++) {
                unsigned t[4];
                ldsm4(t, B + (wn * 64 + jp * 16 + (lane & 7) + ((lane >> 4) & 1) * 8) * 36
                           + ks * 8 + ((lane >> 3) & 1) * 4);
                b[jp * 2][0] = t[0]; b[jp * 2][1] = t[1];
                b[jp * 2 + 1][0] = t[2]; b[jp * 2 + 1][1] = t[3];
            }
#pragma unroll
            for (int i = 0; i < 2; i++)
#pragma unroll
                for (int j = 0; j < 8; j++)
                    mma_tf32(acc[i * 8 + j], a[i], b[j]);
        }
    }

    float bcol[16];
#pragma unroll
    for (int j = 0; j < 8; j++) {
        bcol[j * 2]     = P.b[v][wn * 64 + j * 8 + 2 * tg];
        bcol[j * 2 + 1] = P.b[v][wn * 64 + j * 8 + 2 * tg + 1];
    }
    float ssq[4];
#pragma unroll
    for (int i = 0; i < 2; i++)
#pragma unroll
        for (int hh = 0; hh < 2; hh++) {
            float s = 0.f;
#pragma unroll
            for (int j = 0; j < 8; j++)
#pragma unroll
                for (int e = 0; e < 2; e++) {
                    float t = acc[i * 8 + j][hh * 2 + e] + bcol[j * 2 + e];
                    t = (t >= 0.f) ? t : 0.1f * t;
                    acc[i * 8 + j][hh * 2 + e] = t;
                    s = fmaf(t, t, s);
                }
            ssq[i * 2 + hh] = s;
        }
#pragma unroll
    for (int r4 = 0; r4 < 4; r4++) {
        ssq[r4] += __shfl_xor_sync(0xFFFFFFFFu, ssq[r4], 1);
        ssq[r4] += __shfl_xor_sync(0xFFFFFFFFu, ssq[r4], 2);
    }
    if (tg == 0) {
#pragma unroll
        for (int i = 0; i < 2; i++)
#pragma unroll
            for (int hh = 0; hh < 2; hh++)
                ss[wn][wm * 32 + i * 16 + hh * 8 + g] = ssq[i * 2 + hh];
    }
    __syncthreads();
#pragma unroll
    for (int i = 0; i < 2; i++)
#pragma unroll
        for (int hh = 0; hh < 2; hh++) {
            int lr = wm * 32 + i * 16 + hh * 8 + g;
            int n = rb * 128 + lr;
            float tot = (ss[0][lr] + ss[1][lr]) + (ss[2][lr] + ss[3][lr]);
            float rinv = 1.f / fmaxf(sqrtf(tot), 1e-12f);
            float mrow = (float)P.mask[n * NV + v];
            size_t base = ((size_t)v * NN + n) * HH;
#pragma unroll
            for (int j = 0; j < 8; j++) {
                int col = wn * 64 + j * 8 + 2 * tg;
                float p0 = acc[i * 8 + j][hh * 2];
                float p1 = acc[i * 8 + j][hh * 2 + 1];
                *(float2*)(g_xp + base + col) = make_float2(p0, p1);
                *(float2*)(g_xq + base + col) =
                    make_float2(f2tf_f(p0 * rinv), f2tf_f(p1 * rinv));
                *(float2*)(g_xb + base + col) =
                    make_float2(f2tf_f(p0 * mrow), f2tf_f(p1 * mrow));
            }
        }
}

// ---------------- K2: s (SYMMETRIC upper-tri blocks, 3-stage pipeline) ------
#define SMAT_BUF (128 * 36)
__global__ __launch_bounds__(512, 1) void k_smat_tc(const int* __restrict__ mask) {
    int rem = blockIdx.x, rb = 0;
    while (rem >= 32 - rb) { rem -= 32 - rb; rb++; }
    int cb = rb + rem;

    int tid = threadIdx.x, lane = tid & 31, wid = tid >> 5;
    int wm = wid >> 2, wn = wid & 3;
    int g = lane >> 2, tg = lane & 3;

    extern __shared__ float dyn[];
    float* Abuf = dyn;                     // [3][128*36]
    float* Bbuf = dyn + 3 * SMAT_BUF;      // [3][128*36]

    __shared__ int rm_s[NV][128], cm_s[NV][128];
    for (int l = tid; l < 128; l += 512) {
#pragma unroll
        for (int v = 0; v < NV; v++) {
            rm_s[v][l] = mask[(rb * 128 + l) * NV + v];
            cm_s[v][l] = mask[(cb * 128 + l) * NV + v];
        }
    }

    auto load_chunk = [&](int c, int buf) {
        int v = c >> 3, k0 = (c & 7) * 32;
        const float* xq = g_xq + (size_t)v * NN * HH;
        float* Ab = Abuf + buf * SMAT_BUF;
        float* Bb = Bbuf + buf * SMAT_BUF;
#pragma unroll
        for (int q = 0; q < 2; q++) {
            int l = q * 512 + tid;
            int r = l >> 3, kq = l & 7;
            cp16(Ab + r * 36 + kq * 4, xq + (size_t)(rb * 128 + r) * HH + k0 + kq * 4);
            cp16(Bb + r * 36 + kq * 4, xq + (size_t)(cb * 128 + r) * HH + k0 + kq * 4);
        }
        CP_COMMIT();
    };

    float smax[8][4], dot[8][4];
#pragma unroll
    for (int t = 0; t < 8; t++)
#pragma unroll
        for (int e = 0; e < 4; e++) { smax[t][e] = 0.f; dot[t][e] = 0.f; }

    load_chunk(0, 0);
    load_chunk(1, 1);

    for (int c = 0; c < 24; c++) {
        if (c >= 22) { CP_WAIT0(); } else { CP_WAIT1(); }
        __syncthreads();
        if (c + 2 < 24) load_chunk(c + 2, (c + 2) % 3);

        const float* As = Abuf + (c % 3) * SMAT_BUF;
        const float* Bs = Bbuf + (c % 3) * SMAT_BUF;
#pragma unroll
        for (int ks = 0; ks < 4; ks++) {
            unsigned a[2][4], b[4][2];
#pragma unroll
            for (int i = 0; i < 2; i++)
                ldsm4(a[i], As + (wm * 32 + i * 16 + (lane & 15)) * 36
                              + ks * 8 + ((lane >> 4) & 1) * 4);
#pragma unroll
            for (int jp = 0; jp < 2; jp++) {
                unsigned t[4];
                ldsm4(t, Bs + (wn * 32 + jp * 16 + (lane & 7) + ((lane >> 4) & 1) * 8) * 36
                           + ks * 8 + ((lane >> 3) & 1) * 4);
                b[jp * 2][0] = t[0]; b[jp * 2][1] = t[1];
                b[jp * 2 + 1][0] = t[2]; b[jp * 2 + 1][1] = t[3];
            }
#pragma unroll
            for (int i = 0; i < 2; i++)
#pragma unroll
                for (int j = 0; j < 4; j++)
                    mma_tf32(dot[i * 4 + j], a[i], b[j]);
        }

        if ((c & 7) == 7) {
            int v = c >> 3;
#pragma unroll
            for (int i = 0; i < 2; i++)
#pragma unroll
                for (int j = 0; j < 4; j++) {
                    int t = i * 4 + j;
#pragma unroll
                    for (int e = 0; e < 4; e++) {
                        int rl = wm * 32 + i * 16 + g + ((e >> 1) << 3);
                        int cl = wn * 32 + j * 8 + 2 * tg + (e & 1);
                        if (rm_s[v][rl] && cm_s[v][cl])
                            smax[t][e] = fmaxf(smax[t][e], __expf(dot[t][e] * 5.0f));
                        dot[t][e] = 0.f;
                    }
                }
        }
    }

    // store: direct tile always; off-diagonal also staged transposed in smem
    bool offdiag = (rb != cb);
    float* tile = dyn;                 // reuse pipeline buffers: 128 x 132
    __syncthreads();                   // all reads of dyn are done

#pragma unroll
    for (int i = 0; i < 2; i++)
#pragma unroll
        for (int j = 0; j < 4; j++) {
            int t = i * 4 + j;
#pragma unroll
            for (int h = 0; h < 2; h++) {
                int rl  = wm * 32 + i * 16 + g + h * 8;
                int cl  = wn * 32 + j * 8 + 2 * tg;
                int n   = rb * 128 + rl;
                int col = cb * 128 + cl;
                float v0 = f2tf_f(smax[t][h * 2 + 0]);
                float v1 = f2tf_f(smax[t][h * 2 + 1]);
                if (n == col)     v0 = 0.f;
                if (n == col + 1) v1 = 0.f;
                *(float2*)(g_s + (size_t)n * NN + col) = make_float2(v0, v1);
                if (offdiag) {
                    tile[cl * 132 + rl]       = v0;
                    tile[(cl + 1) * 132 + rl] = v1;
                }
            }
        }

    if (offdiag) {
        __syncthreads();
#pragma unroll
        for (int q = 0; q < 8; q++) {          // 128 rows x 32 float4
            int l = q * 512 + tid;
            int r = l >> 5, c4 = l & 31;
            float4 f = *(const float4*)&tile[r * 132 + c4 * 4];
            *(float4*)(g_s + (size_t)(cb * 128 + r) * NN + rb * 128 + c4 * 4) = f;
        }
    }
}

// ---------------- K3: rowsum + confi (int4 mask loads) ----------------------
__global__ void k_rowstats(const int* __restrict__ mask, float* __restrict__ confi_out) {
    int n = blockIdx.x;
    int tid = threadIdx.x;
    const float4* srow = (const float4*)(g_s + (size_t)n * NN);
    const int4* m4p = (const int4*)mask;
    float sum = 0.f, x0 = 0.f, x1 = 0.f, x2 = 0.f;
    for (int m4 = tid; m4 < NN / 4; m4 += 256) {
        float4 sv = srow[m4];
        int4 ma = m4p[m4 * 3 + 0];
        int4 mb = m4p[m4 * 3 + 1];
        int4 mc = m4p[m4 * 3 + 2];
        sum += (sv.x + sv.y) + (sv.z + sv.w);
        if (ma.x) x0 = fmaxf(x0, sv.x);
        if (ma.y) x1 = fmaxf(x1, sv.x);
        if (ma.z) x2 = fmaxf(x2, sv.x);
        if (ma.w) x0 = fmaxf(x0, sv.y);
        if (mb.x) x1 = fmaxf(x1, sv.y);
        if (mb.y) x2 = fmaxf(x2, sv.y);
        if (mb.z) x0 = fmaxf(x0, sv.z);
        if (mb.w) x1 = fmaxf(x1, sv.z);
        if (mc.x) x2 = fmaxf(x2, sv.z);
        if (mc.y) x0 = fmaxf(x0, sv.w);
        if (mc.z) x1 = fmaxf(x1, sv.w);
        if (mc.w) x2 = fmaxf(x2, sv.w);
    }
    __shared__ float rs0[256], rs1[256], rs2[256], rs3[256];
    rs0[tid] = sum; rs1[tid] = x0; rs2[tid] = x1; rs3[tid] = x2;
    __syncthreads();
    for (int off = 128; off > 0; off >>= 1) {
        if (tid < off) {
            rs0[tid] += rs0[tid + off];
            rs1[tid] = fmaxf(rs1[tid], rs1[tid + off]);
            rs2[tid] = fmaxf(rs2[tid], rs2[tid + off]);
            rs3[tid] = fmaxf(rs3[tid], rs3[tid + off]);
        }
        __syncthreads();
    }
    if (tid == 0) {
        g_rowsum[n] = rs0[0];
        confi_out[0 * NN + n] = fminf(fmaxf(0.2f * __logf(rs1[0] + 1e-9f), 0.f), 1.f);
        confi_out[1 * NN + n] = fminf(fmaxf(0.2f * __logf(rs2[0] + 1e-9f), 0.f), 1.f);
        confi_out[2 * NN + n] = fminf(fmaxf(0.2f * __logf(rs3[0] + 1e-9f), 0.f), 1.f);
    }
}

// ---------------- K4: new_x = (s/rowsum) @ xb_v -> blend -> Z ---------------
// Block 64 rows x 128 h, 8 warps 2x4, warp 32x32, 2 blocks/SM, 3-stage.
// B from k-major g_xb (contiguous 512B row segments), scalar b-loads.
#define NX_ABUF (64 * 36)
#define NX_BBUF (32 * 136)
#define NX_STG  (NX_ABUF + NX_BBUF)
__global__ __launch_bounds__(256, 2) void k_newx_tc(const int* __restrict__ mask,
                                                    float* __restrict__ out) {
    int rb = blockIdx.x, hb = blockIdx.y, v = blockIdx.z;
    int h0 = hb * 128;
    int tid = threadIdx.x, lane = tid & 31, wid = tid >> 5;
    int wm = wid >> 2, wn = wid & 3;
    int g = lane >> 2, tg = lane & 3;

    extern __shared__ float dyn[];
    // 3 stages, each [A(64*36) | B(32*136)]
    __shared__ float yns[CC * 128];

    for (int l = tid; l < CC * 128; l += 256)
        yns[l] = g_yn[(l >> 7) * HH + h0 + (l & 127)];

    const float* xb = g_xb + (size_t)v * NN * HH;

    auto load_chunk = [&](int c, int buf) {
        int m0 = c * 32;
        float* Ab = dyn + buf * NX_STG;
        float* Bb = Ab + NX_ABUF;
#pragma unroll
        for (int q = 0; q < 2; q++) {            // A: 64 x 32
            int l = q * 256 + tid;
            int r = l >> 3, kq = l & 7;
            cp16(Ab + r * 36 + kq * 4, g_s + (size_t)(rb * 64 + r) * NN + m0 + kq * 4);
        }
#pragma unroll
        for (int q = 0; q < 4; q++) {            // B: 32 k-rows x 128 h
            int l = q * 256 + tid;
            int kr = l >> 5, c4 = l & 31;
            cp16(Bb + kr * 136 + c4 * 4, xb + (size_t)(m0 + kr) * HH + h0 + c4 * 4);
        }
        CP_COMMIT();
    };

    float acc[8][4];
#pragma unroll
    for (int t = 0; t < 8; t++)
#pragma unroll
        for (int e = 0; e < 4; e++) acc[t][e] = 0.f;

    load_chunk(0, 0);
    load_chunk(1, 1);

    const int NC = NN / 32;
    for (int c = 0; c < NC; c++) {
        if (c >= NC - 2) { CP_WAIT0(); } else { CP_WAIT1(); }
        __syncthreads();
        if (c + 2 < NC) load_chunk(c + 2, (c + 2) % 3);

        const float* As = dyn + (c % 3) * NX_STG;
        const float* Bs = As + NX_ABUF;
#pragma unroll
        for (int ks = 0; ks < 4; ks++) {
            unsigned a[2][4], b[4][2];
#pragma unroll
            for (int i = 0; i < 2; i++)
                ldsm4(a[i], As + (wm * 32 + i * 16 + (lane & 15)) * 36
                              + ks * 8 + ((lane >> 4) & 1) * 4);
            const unsigned* Bu = (const unsigned*)Bs;
#pragma unroll
            for (int j = 0; j < 4; j++) {
                int cc = wn * 32 + j * 8 + g;
                b[j][0] = Bu[(ks * 8 + tg) * 136 + cc];
                b[j][1] = Bu[(ks * 8 + tg + 4) * 136 + cc];
            }
#pragma unroll
            for (int i = 0; i < 2; i++)
#pragma unroll
                for (int j = 0; j < 4; j++)
                    mma_tf32(acc[i * 4 + j], a[i], b[j]);
        }
    }

    // epilogue: rowsum scale, mask blend, y_n expansion to Z
#pragma unroll
    for (int i = 0; i < 2; i++)
#pragma unroll
        for (int hh = 0; hh < 2; hh++) {
            int n = rb * 64 + wm * 32 + i * 16 + g + hh * 8;
            float rinv = 1.f / (g_rowsum[n] + 1e-9f);
            int mrow = mask[n * NV + v];
            float nx[8];
            if (mrow) {
                const float* xpr = g_xp + ((size_t)v * NN + n) * HH + h0;
#pragma unroll
                for (int j = 0; j < 4; j++) {
                    float2 p = *(const float2*)(xpr + wn * 32 + j * 8 + 2 * tg);
                    nx[j * 2] = p.x; nx[j * 2 + 1] = p.y;
                }
            } else {
#pragma unroll
                for (int j = 0; j < 4; j++) {
                    nx[j * 2]     = acc[i * 4 + j][hh * 2]     * rinv;
                    nx[j * 2 + 1] = acc[i * 4 + j][hh * 2 + 1] * rinv;
                }
            }
            size_t zbase = ((size_t)v * NN + n) * (CC * HH) + h0;
#pragma unroll
            for (int c = 0; c < CC; c++) {
#pragma unroll
                for (int j = 0; j < 4; j++) {
                    int col = wn * 32 + j * 8 + 2 * tg;
                    float2 yv = *(const float2*)&yns[c * 128 + col];
                    *(float2*)(out + zbase + (size_t)c * HH + col) =
                        make_float2(nx[j * 2] * yv.x, nx[j * 2 + 1] * yv.y);
                }
            }
        }
}

// ---------------- launch ----------------------------------------------------
extern "C" void kernel_launch(void* const* d_in, const int* in_sizes, int n_in,
                              void* d_out, int out_size) {
    ProjPtrs P{};
    RoundPtrs R{};
    const float* yv  = nullptr;
    const float* Wy  = nullptr;
    const float* byp = nullptr;
    const int*   mask = nullptr;
    int nx = 0, nW = 0, nb = 0;
    for (int i = 0; i < n_in; i++) {
        int s = in_sizes[i];
        if      (s == NN * DD)  { if (nx < NV) R.x[nx++] = (const float*)d_in[i]; }
        else if (s == HH * DD)  { if (nW < NV) R.W[nW++] = (const float*)d_in[i]; }
        else if (s == CC * DYY) yv = (const float*)d_in[i];
        else if (s == HH * DYY) Wy = (const float*)d_in[i];
        else if (s == NN * NV)  mask = (const int*)d_in[i];
        else if (s == HH) {
            if (nb < NV) P.b[nb++] = (const float*)d_in[i];
            else         byp = (const float*)d_in[i];
        }
    }
    P.mask = mask;
    float* out = (float*)d_out;
    float* confi_out = out + ((size_t)out_size - (size_t)NV * NN);

    const int proj_dyn = 2 * (PROJ_ABUF + PROJ_BBUF) * (int)sizeof(float);  // 110592
    const int smat_dyn = 6 * SMAT_BUF * (int)sizeof(float);                 // 110592
    const int newx_dyn = 3 * NX_STG * (int)sizeof(float);                   // 79872
    cudaFuncSetAttribute(k_proj_tc, cudaFuncAttributeMaxDynamicSharedMemorySize, proj_dyn);
    cudaFuncSetAttribute(k_smat_tc, cudaFuncAttributeMaxDynamicSharedMemorySize, smat_dyn);
    cudaFuncSetAttribute(k_newx_tc, cudaFuncAttributeMaxDynamicSharedMemorySize, newx_dyn);

    int round_total = 3 * (NN * DD / 4) + 3 * (HH * DD / 4);
    k_round   <<<(round_total + 255) / 256, 256>>>(R);
    k_yn      <<<CC, HH>>>(yv, Wy, byp);
    k_proj_tc <<<dim3(NN / 128, NV), 512, proj_dyn>>>(P);
    k_smat_tc <<<528, 512, smat_dyn>>>(mask);
    k_rowstats<<<NN, 256>>>(mask, confi_out);
    k_newx_tc <<<dim3(NN / 64, HH / 128, NV), 256, newx_dyn>>>(mask, out);
}